// round 16
// baseline (speedup 1.0000x reference)
#include <cuda_runtime.h>
#include <cuda_fp16.h>
#include <math.h>
#include <string.h>

// ---------------- problem constants ----------------
#define NB 8192
#define IN1 384          // padded folded feature count (378 effective)
#define IN1_EFF 378

typedef unsigned long long ull;

// ---------------- device scratch (no allocations allowed) ----------------
__device__ float g_h0[NB * IN1];
__device__ float g_h1[NB * 80];
__device__ float g_h2[NB * 160];
__device__ float g_h3[NB * 80];
__device__ float g_h4[NB * 40];
__device__ float g_tw[576];    // twiddles: cos [0,288), sin [288,576)

// packed fp32 base weights: float4 per (i, u, lane) holds slots o = lane + (u*4+s)*32
__device__ float4 g_wb1[IN1 * 1 * 32];    // OUT=80,  NU4=1
__device__ float4 g_wb2[80 * 2 * 32];     // OUT=160, NU4=2
__device__ float4 g_wb3[160 * 1 * 32];    // OUT=80,  NU4=1
__device__ float4 g_wb4[80 * 1 * 32];     // OUT=40,  NU4=1

// packed fp16 spline weights: 4 coeffs per (entry, out) = uint2
__device__ uint2 g_w4_1[IN1 * 16 * 80];
__device__ uint2 g_w4_2[80 * 16 * 160];
__device__ uint2 g_w4_3[160 * 16 * 80];
__device__ uint2 g_w4_4[80 * 16 * 40];

// ---------------- f32x2 helpers ----------------
__device__ __forceinline__ void ffma2(ull& d, ull a, ull b) {
    asm("fma.rn.f32x2 %0, %1, %2, %0;" : "+l"(d) : "l"(a), "l"(b));
}
__device__ __forceinline__ ull dup2(float w) {
    ull r;
    asm("mov.b64 %0, {%1, %1};" : "=l"(r) : "f"(w));
    return r;
}
__device__ __forceinline__ float2 u2f2(ull v) {
    float2 f;
    memcpy(&f, &v, 8);
    return f;
}
__device__ __forceinline__ __half2 uh2(unsigned v) {
    __half2 h;
    memcpy(&h, &v, 4);
    return h;
}

// ---------------- prep helpers ----------------
__device__ __forceinline__ void store_w16(uint2* __restrict__ w4, int e, int o, int OUT,
                                          const float* w) {
#pragma unroll
    for (int j = 0; j < 16; j++) {
        int c0 = j - 3;
        float vx = (c0 >= 0 && c0 < 13) ? w[c0] : 0.f;
        float vy = (c0 + 1 >= 0 && c0 + 1 < 13) ? w[c0 + 1] : 0.f;
        float vz = (c0 + 2 >= 0 && c0 + 2 < 13) ? w[c0 + 2] : 0.f;
        float vw = (c0 + 3 >= 0 && c0 + 3 < 13) ? w[c0 + 3] : 0.f;
        __half2 h01 = __floats2half2_rn(vx, vy);
        __half2 h23 = __floats2half2_rn(vz, vw);
        uint2 u;
        u.x = *(unsigned*)&h01;
        u.y = *(unsigned*)&h23;
        w4[(e * 16 + j) * OUT + o] = u;
    }
}

__device__ __forceinline__ void store_wb(float4* __restrict__ wb, int i, int o_slot,
                                         int NU4, float v) {
    int lane = o_slot & 31;
    int t = o_slot >> 5;
    int u = t >> 2;
    int s = t & 3;
    ((float*)wb)[((size_t)(i * NU4 + u) * 32 + lane) * 4 + s] = v;
}

// layer-1 prep: fold duplicated angle features (exact); thread per (e, o_slot<128)
__global__ void prep_l1_kernel(const float* __restrict__ base,
                               const float* __restrict__ spline,
                               const float* __restrict__ scaler,
                               float4* __restrict__ wb,
                               uint2* __restrict__ w4) {
    int tid = blockIdx.x * blockDim.x + threadIdx.x;
    if (tid >= IN1 * 128) return;
    int o_slot = tid & 127;
    int e = tid >> 7;
    if (e >= IN1_EFF || o_slot >= 80) {
        store_wb(wb, e, o_slot, 1, 0.f);
        return;
    }
    int o = o_slot;
    int ch = e / 27, m = e % 27;
    int i = ch * 36 + m;
    float sc = scaler[o * 504 + i];
    const float* sp = spline + (size_t)(o * 504 + i) * 13;
    float w[13];
#pragma unroll
    for (int c = 0; c < 13; c++) w[c] = sp[c] * sc;
    float bsum = base[o * 504 + i];
    if (m >= 9 && m < 18) {
        int i2 = i + 18;
        float sc2 = scaler[o * 504 + i2];
        const float* sp2 = spline + (size_t)(o * 504 + i2) * 13;
#pragma unroll
        for (int c = 0; c < 13; c++) w[c] += sp2[c] * sc2;
        bsum += base[o * 504 + i2];
    }
    store_wb(wb, e, o_slot, 1, bsum);
    store_w16(w4, e, o, 80, w);
}

// layers 2-4 merged prep + twiddle fill; thread per (i, o_slot)
__global__ void prep3_kernel(const float* __restrict__ b2, const float* __restrict__ s2, const float* __restrict__ c2,
                             const float* __restrict__ b3, const float* __restrict__ s3, const float* __restrict__ c3,
                             const float* __restrict__ b4, const float* __restrict__ s4, const float* __restrict__ c4,
                             float4* __restrict__ wb2, uint2* __restrict__ w42,
                             float4* __restrict__ wb3, uint2* __restrict__ w43,
                             float4* __restrict__ wb4, uint2* __restrict__ w44,
                             float* __restrict__ tw) {
    int tid = blockIdx.x * blockDim.x + threadIdx.x;
    const int N2 = 80 * 256, N3 = 160 * 128, N4 = 80 * 128;
    const int NTOT = N2 + N3 + N4;
    if (tid >= NTOT) {
        int t2 = tid - NTOT;
        if (t2 < 288) {
            int k = t2 >> 5, n = t2 & 31;
            float s, c;
            sincospif((float)(k * n) * (1.0f / 16.0f), &s, &c);
            tw[t2] = c;
            tw[t2 + 288] = s;
        }
        return;
    }
    const float *base, *spline, *scaler;
    float4* wb;
    uint2* w4;
    int IN, OUT, NU4, local;
    if (tid < N2) {
        base = b2; spline = s2; scaler = c2; wb = wb2; w4 = w42; IN = 80; OUT = 160; NU4 = 2; local = tid;
    } else if (tid < N2 + N3) {
        base = b3; spline = s3; scaler = c3; wb = wb3; w4 = w43; IN = 160; OUT = 80; NU4 = 1; local = tid - N2;
    } else {
        base = b4; spline = s4; scaler = c4; wb = wb4; w4 = w44; IN = 80; OUT = 40; NU4 = 1; local = tid - N2 - N3;
    }
    int SLOTS = NU4 * 128;
    int o_slot = local % SLOTS;
    int i = local / SLOTS;
    if (o_slot >= OUT) {
        store_wb(wb, i, o_slot, NU4, 0.f);
        return;
    }
    int o = o_slot;
    store_wb(wb, i, o_slot, NU4, base[o * IN + i]);
    float sc = scaler[o * IN + i];
    const float* sp = spline + (size_t)(o * IN + i) * 13;
    float w[13];
#pragma unroll
    for (int c = 0; c < 13; c++) w[c] = sp[c] * sc;
    store_w16(w4, i, o, OUT, w);
}

// ---------------- FFT feature kernel: transposed smem, conflict-free inner loop ----------------
__global__ void fft_kernel(const float* __restrict__ x, const float* __restrict__ tw,
                           float* __restrict__ h0) {
    __shared__ float sx[64][17];    // [n][c]: lanes differ in c -> distinct banks
    __shared__ float sco[32][12];   // [n][k]: lanes differ in k -> distinct banks
    __shared__ float ssi[32][12];
    int b = blockIdx.x;
    int t = threadIdx.x;
    const float* xb = x + (size_t)b * 896;
    for (int i = t; i < 896; i += 128) {
        int c = i / 64, n = i % 64;
        sx[n][c] = xb[i];
    }
    for (int i = t; i < 384; i += 128) {
        int n = i / 12, k = i % 12;
        float cv = 0.f, sv = 0.f;
        if (k < 9) {
            cv = __ldg(&tw[k * 32 + n]);
            sv = __ldg(&tw[288 + k * 32 + n]);
        }
        sco[n][k] = cv;
        ssi[n][k] = sv;
    }
    __syncthreads();
    if (t < 6) h0[(size_t)b * IN1 + IN1_EFF + t] = -1e9f;
    if (t < 126) {
        int c = t / 9, k = t % 9;
        float pr = 0.f, pi = 0.f, cr = 0.f, ci = 0.f;
#pragma unroll
        for (int n = 0; n < 32; n++) {
            float co = sco[n][k], si = ssi[n][k];
            float a = sx[n][c], d = sx[n + 32][c];
            pr += a * co; pi -= a * si;
            cr += d * co; ci -= d * si;
        }
        float abs_p = sqrtf(pr * pr + pi * pi);
        float abs_c = sqrtf(cr * cr + ci * ci);
        float ang_c = atan2f(ci, cr);
        float* o = h0 + (size_t)b * IN1 + c * 27;
        o[k] = abs_p;
        o[9 + k] = ang_c;
        o[18 + k] = abs_c;
    }
}

// ---------------- base path v6: 4-way split-K, 8 rows/warp, f32x2 packed FMA ----------------
// ADD=true: accumulate into existing out (used when spline ran first)
template <int IN, int OUT, int NO, int NU4, bool ADD>
__global__ void __launch_bounds__(256) base_gemm6(const float* __restrict__ xin,
                                                  const float4* __restrict__ wbp,
                                                  float* __restrict__ out) {
    __shared__ __align__(16) float ss[IN][20];   // [i][row 0..15], pad 4
    __shared__ float2 pacc[3][8][NO * 32];       // partials from splits 1..3, per row-pair
    int b0 = blockIdx.x * 16;
    int tid = threadIdx.x;
    constexpr int NF4 = IN / 4;
    {
        int r = tid & 15;
        const float4* xp = (const float4*)(xin + (size_t)(b0 + r) * IN);
        for (int i4 = tid >> 4; i4 < NF4; i4 += 16) {
            float4 v = xp[i4];
            v.x = v.x / (1.f + __expf(-v.x));
            v.y = v.y / (1.f + __expf(-v.y));
            v.z = v.z / (1.f + __expf(-v.z));
            v.w = v.w / (1.f + __expf(-v.w));
            ss[i4 * 4 + 0][r] = v.x;
            ss[i4 * 4 + 1][r] = v.y;
            ss[i4 * 4 + 2][r] = v.z;
            ss[i4 * 4 + 3][r] = v.w;
        }
    }
    __syncthreads();

    int w = tid >> 5, lane = tid & 31;
    int rg = w & 1;
    int sp = w >> 1;
    int r0 = rg * 8;
    constexpr int KH = IN / 4;
    int istart = sp * KH;

    ull acc[4][NO];   // [row-pair][slot], packed (even,odd) rows
#pragma unroll
    for (int pp = 0; pp < 4; pp++)
#pragma unroll
        for (int q = 0; q < NO; q++) acc[pp][q] = 0ull;

#pragma unroll 4
    for (int ii = 0; ii < KH; ii++) {
        int i = istart + ii;
        longlong2 sa = *(const longlong2*)&ss[i][r0];       // (s0,s1),(s2,s3)
        longlong2 sb = *(const longlong2*)&ss[i][r0 + 4];   // (s4,s5),(s6,s7)
#pragma unroll
        for (int u = 0; u < NU4; u++) {
            float4 wv = __ldg(&wbp[(size_t)(i * NU4 + u) * 32 + lane]);
#pragma unroll
            for (int c = 0; c < 4; c++) {
                int q = u * 4 + c;
                if (q < NO) {
                    float wf = (c == 0) ? wv.x : (c == 1) ? wv.y : (c == 2) ? wv.z : wv.w;
                    ull wd = dup2(wf);
                    ffma2(acc[0][q], (ull)sa.x, wd);
                    ffma2(acc[1][q], (ull)sa.y, wd);
                    ffma2(acc[2][q], (ull)sb.x, wd);
                    ffma2(acc[3][q], (ull)sb.y, wd);
                }
            }
        }
    }

    if (sp > 0) {
#pragma unroll
        for (int pp = 0; pp < 4; pp++)
#pragma unroll
            for (int q = 0; q < NO; q++)
                pacc[sp - 1][rg * 4 + pp][lane + q * 32] = u2f2(acc[pp][q]);
    }
    __syncthreads();
    if (sp == 0) {
#pragma unroll
        for (int pp = 0; pp < 4; pp++) {
#pragma unroll
            for (int q = 0; q < NO; q++) {
                int o = lane + q * 32;
                if (o < OUT) {
                    int idx = lane + q * 32;
                    int rp = rg * 4 + pp;
                    float2 t = u2f2(acc[pp][q]);
                    float2 p0 = pacc[0][rp][idx];
                    float2 p1 = pacc[1][rp][idx];
                    float2 p2 = pacc[2][rp][idx];
                    size_t o0 = (size_t)(b0 + r0 + pp * 2 + 0) * OUT + o;
                    size_t o1 = (size_t)(b0 + r0 + pp * 2 + 1) * OUT + o;
                    float v0 = t.x + p0.x + p1.x + p2.x;
                    float v1 = t.y + p0.y + p1.y + p2.y;
                    if (ADD) {
                        out[o0] = v0 + out[o0];
                        out[o1] = v1 + out[o1];
                    } else {
                        out[o0] = v0;
                        out[o1] = v1;
                    }
                }
            }
        }
    }
}

// ---------------- spline path v4: 2-way entry split per row, fp16 bases, HFMA2 inner ----------------
// block = 128 thr = 4 warps = 2 rows x 2 entry-halves. Half 1 dumps partials; half 0 combines.
// INIT=true: start acc from 0 (runs before base, which then adds)
template <int IN, int IEFF, int OUT, int NO, bool INIT>
__global__ void __launch_bounds__(128, 8) spline_kernel(const float* __restrict__ xin,
                                                        const uint2* __restrict__ w4,
                                                        float* __restrict__ out) {
    constexpr int R = 2;                                   // rows per block
    constexpr int MID = ((IEFF / 2 + 31) / 32) * 32;       // half boundary (mult of 32)
    constexpr int MAXE = MID;                              // max entries per half
    __shared__ uint2 sbs[R][2][MAXE];
    __shared__ int scode[R][2][MAXE];
    __shared__ float spacc[R][NO * 32];
    int w = threadIdx.x >> 5;
    int lane = threadIdx.x & 31;
    int r = w >> 1;
    int half = w & 1;
    int b = blockIdx.x * R + r;
    const float* xr = xin + (size_t)b * IN;

    int istart = half ? MID : 0;
    int iend = half ? IEFF : MID;

    int cnt = 0;
    for (int i0 = istart; i0 < iend; i0 += 32) {
        int i = i0 + lane;
        bool valid = false;
        int j = 0;
        float4 bs = make_float4(0.f, 0.f, 0.f, 0.f);
        if (i < iend) {
            float xv = xr[i];
            float u = (xv + 0.3f) * 10.0f;
            j = (int)floorf(u);
            if (j >= 0 && j <= 15) {
                float gj = (float)(j - 3) * 0.1f;
                float t = (xv - gj) * 10.0f;
                float t2 = t * t, t3 = t2 * t;
                float omt = 1.f - t;
                bs.x = omt * omt * omt * (1.f / 6.f);
                bs.y = (3.f * t3 - 6.f * t2 + 4.f) * (1.f / 6.f);
                bs.z = (-3.f * t3 + 3.f * t2 + 3.f * t + 1.f) * (1.f / 6.f);
                bs.w = t3 * (1.f / 6.f);
                valid = true;
            }
        }
        unsigned m = __ballot_sync(0xffffffffu, valid);
        int pos = cnt + __popc(m & ((1u << lane) - 1u));
        if (valid) {
            scode[r][half][pos] = i * 16 + j;
            __half2 h01 = __floats2half2_rn(bs.x, bs.y);
            __half2 h23 = __floats2half2_rn(bs.z, bs.w);
            uint2 u;
            u.x = *(unsigned*)&h01;
            u.y = *(unsigned*)&h23;
            sbs[r][half][pos] = u;
        }
        cnt += __popc(m);
    }
    __syncwarp();

    float acc[NO];
#pragma unroll
    for (int q = 0; q < NO; q++) acc[q] = 0.f;

    int e = 0;
    for (; e + 4 <= cnt; e += 4) {
        int cs[4];
        __half2 b01[4], b23[4];
        const uint2* wp[4];
#pragma unroll
        for (int k = 0; k < 4; k++) {
            cs[k] = scode[r][half][e + k];
            uint2 ub = sbs[r][half][e + k];
            b01[k] = uh2(ub.x);
            b23[k] = uh2(ub.y);
            wp[k] = w4 + (size_t)cs[k] * OUT;
        }
#pragma unroll
        for (int q = 0; q < NO; q++) {
            int o = lane + q * 32;
            int oc = (o < OUT) ? o : (OUT - 1);
            uint2 u0 = __ldg(&wp[0][oc]);
            uint2 u1 = __ldg(&wp[1][oc]);
            uint2 u2 = __ldg(&wp[2][oc]);
            uint2 u3 = __ldg(&wp[3][oc]);
            __half2 hacc = __floats2half2_rn(0.f, 0.f);
            hacc = __hfma2(uh2(u0.x), b01[0], hacc);
            hacc = __hfma2(uh2(u0.y), b23[0], hacc);
            hacc = __hfma2(uh2(u1.x), b01[1], hacc);
            hacc = __hfma2(uh2(u1.y), b23[1], hacc);
            hacc = __hfma2(uh2(u2.x), b01[2], hacc);
            hacc = __hfma2(uh2(u2.y), b23[2], hacc);
            hacc = __hfma2(uh2(u3.x), b01[3], hacc);
            hacc = __hfma2(uh2(u3.y), b23[3], hacc);
            float2 f = __half22float2(hacc);
            if (o < OUT) acc[q] += f.x + f.y;
        }
    }
    for (; e < cnt; e++) {
        int c0 = scode[r][half][e];
        uint2 ub = sbs[r][half][e];
        __half2 b01 = uh2(ub.x);
        __half2 b23 = uh2(ub.y);
        const uint2* w0 = w4 + (size_t)c0 * OUT;
#pragma unroll
        for (int q = 0; q < NO; q++) {
            int o = lane + q * 32;
            int oc = (o < OUT) ? o : (OUT - 1);
            uint2 ua = __ldg(&w0[oc]);
            __half2 hacc = __floats2half2_rn(0.f, 0.f);
            hacc = __hfma2(uh2(ua.x), b01, hacc);
            hacc = __hfma2(uh2(ua.y), b23, hacc);
            float2 f = __half22float2(hacc);
            if (o < OUT) acc[q] += f.x + f.y;
        }
    }

    if (half == 1) {
#pragma unroll
        for (int q = 0; q < NO; q++)
            spacc[r][lane + q * 32] = acc[q];
    }
    __syncthreads();
    if (half == 0) {
#pragma unroll
        for (int q = 0; q < NO; q++) {
            int o = lane + q * 32;
            if (o < OUT) {
                float v = acc[q] + spacc[r][lane + q * 32];
                if (!INIT) v += out[(size_t)b * OUT + o];
                out[(size_t)b * OUT + o] = v;
            }
        }
    }
}

// ---------------- heads: 3 small MLPs, weights staged in shared ----------------
__global__ void heads_kernel(const float* __restrict__ h4,
                             const float* __restrict__ W1, const float* __restrict__ b1,
                             const float* __restrict__ W2, const float* __restrict__ b2,
                             const float* __restrict__ W3, const float* __restrict__ b3,
                             float* __restrict__ out) {
    int head = blockIdx.y;
    __shared__ float sW1[1600], sb1v[40], sW2[800], sb2v[20], sW3[20];
    int t = threadIdx.x;
    for (int i = t; i < 1600; i += 128) sW1[i] = W1[head * 1600 + i];
    for (int i = t; i < 800; i += 128) sW2[i] = W2[head * 800 + i];
    if (t < 40) sb1v[t] = b1[head * 40 + t];
    if (t < 20) {
        sb2v[t] = b2[head * 20 + t];
        sW3[t] = W3[head * 20 + t];
    }
    __syncthreads();
    int b = blockIdx.x * 128 + t;
    float hv[40];
    const float4* hp = (const float4*)(h4 + (size_t)b * 40);
#pragma unroll
    for (int i = 0; i < 10; i++) {
        float4 v = hp[i];
        hv[i * 4 + 0] = v.x; hv[i * 4 + 1] = v.y; hv[i * 4 + 2] = v.z; hv[i * 4 + 3] = v.w;
    }
    float y1[40];
#pragma unroll
    for (int j = 0; j < 40; j++) {
        float s = sb1v[j];
#pragma unroll
        for (int k = 0; k < 40; k++) s += sW1[j * 40 + k] * hv[k];
        y1[j] = s;  // LeakyReLU(True) -> slope 1 -> identity
    }
    float y3 = b3[head];
#pragma unroll
    for (int j = 0; j < 20; j++) {
        float s = sb2v[j];
#pragma unroll
        for (int k = 0; k < 40; k++) s += sW2[j * 40 + k] * y1[k];
        s = (s >= 0.f) ? s : 0.05f * s;
        y3 += sW3[j] * s;
    }
    out[(size_t)b * 3 + head] = 1.f / (1.f + __expf(-y3));
}

// ---------------- launch ----------------
extern "C" void kernel_launch(void* const* d_in, const int* in_sizes, int n_in,
                              void* d_out, int out_size) {
    const float* x   = (const float*)d_in[0];
    const float* k1b = (const float*)d_in[1];
    const float* k1s = (const float*)d_in[2];
    const float* k1c = (const float*)d_in[3];
    const float* k2b = (const float*)d_in[4];
    const float* k2s = (const float*)d_in[5];
    const float* k2c = (const float*)d_in[6];
    const float* k3b = (const float*)d_in[7];
    const float* k3s = (const float*)d_in[8];
    const float* k3c = (const float*)d_in[9];
    const float* k4b = (const float*)d_in[10];
    const float* k4s = (const float*)d_in[11];
    const float* k4c = (const float*)d_in[12];
    const float* hW1 = (const float*)d_in[13];
    const float* hb1 = (const float*)d_in[14];
    const float* hW2 = (const float*)d_in[15];
    const float* hb2 = (const float*)d_in[16];
    const float* hW3 = (const float*)d_in[17];
    const float* hb3 = (const float*)d_in[18];
    float* out = (float*)d_out;

    float *h0, *h1, *h2, *h3, *h4, *tw;
    float4 *wb1, *wb2, *wb3, *wb4;
    uint2 *w41, *w42, *w43, *w44;
    cudaGetSymbolAddress((void**)&h0, g_h0);
    cudaGetSymbolAddress((void**)&h1, g_h1);
    cudaGetSymbolAddress((void**)&h2, g_h2);
    cudaGetSymbolAddress((void**)&h3, g_h3);
    cudaGetSymbolAddress((void**)&h4, g_h4);
    cudaGetSymbolAddress((void**)&tw, g_tw);
    cudaGetSymbolAddress((void**)&wb1, g_wb1);
    cudaGetSymbolAddress((void**)&wb2, g_wb2);
    cudaGetSymbolAddress((void**)&wb3, g_wb3);
    cudaGetSymbolAddress((void**)&wb4, g_wb4);
    cudaGetSymbolAddress((void**)&w41, g_w4_1);
    cudaGetSymbolAddress((void**)&w42, g_w4_2);
    cudaGetSymbolAddress((void**)&w43, g_w4_3);
    cudaGetSymbolAddress((void**)&w44, g_w4_4);

    prep_l1_kernel<<<(IN1 * 128 + 255) / 256, 256>>>(k1b, k1s, k1c, wb1, w41);
    prep3_kernel<<<(80 * 256 + 160 * 128 + 80 * 128 + 288 + 255) / 256, 256>>>(
        k2b, k2s, k2c, k3b, k3s, k3c, k4b, k4s, k4c,
        wb2, w42, wb3, w43, wb4, w44, tw);

    fft_kernel<<<NB, 128>>>(x, tw, h0);

    // layer 1: spline first (launch #4 -> ncu capture), base adds
    spline_kernel<IN1, IN1_EFF, 80, 3, true><<<NB / 2, 128>>>(h0, w41, h1);
    base_gemm6<IN1, 80, 3, 1, true><<<NB / 16, 256>>>(h0, wb1, h1);

    base_gemm6<80, 160, 5, 2, false><<<NB / 16, 256>>>(h1, wb2, h2);
    spline_kernel<80, 80, 160, 5, false><<<NB / 2, 128>>>(h1, w42, h2);

    base_gemm6<160, 80, 3, 1, false><<<NB / 16, 256>>>(h2, wb3, h3);
    spline_kernel<160, 160, 80, 3, false><<<NB / 2, 128>>>(h2, w43, h3);

    base_gemm6<80, 40, 2, 1, false><<<NB / 16, 256>>>(h3, wb4, h4);
    spline_kernel<80, 80, 40, 2, false><<<NB / 2, 128>>>(h3, w44, h4);

    heads_kernel<<<dim3(NB / 128, 3), 128>>>(h4, hW1, hb1, hW2, hb2, hW3, hb3, out);
}

// round 17
// speedup vs baseline: 1.0690x; 1.0690x over previous
#include <cuda_runtime.h>
#include <cuda_fp16.h>
#include <math.h>
#include <string.h>

// ---------------- problem constants ----------------
#define NB 8192
#define IN1 384          // padded folded feature count (378 effective)
#define IN1_EFF 378

typedef unsigned long long ull;

// ---------------- device scratch (no allocations allowed) ----------------
__device__ float g_h0[NB * IN1];
__device__ float g_h1[NB * 80];
__device__ float g_h2[NB * 160];
__device__ float g_h3[NB * 80];
__device__ float g_h4[NB * 40];
__device__ float g_tw[576];    // twiddles: cos [0,288), sin [288,576)

// packed fp32 base weights: float4 per (i, u, lane) holds slots o = lane + (u*4+s)*32
__device__ float4 g_wb1[IN1 * 1 * 32];    // OUT=80,  NU4=1
__device__ float4 g_wb2[80 * 2 * 32];     // OUT=160, NU4=2
__device__ float4 g_wb3[160 * 1 * 32];    // OUT=80,  NU4=1
__device__ float4 g_wb4[80 * 1 * 32];     // OUT=40,  NU4=1

// packed fp16 spline weights: 4 coeffs per (entry, out) = uint2
__device__ uint2 g_w4_1[IN1 * 16 * 80];
__device__ uint2 g_w4_2[80 * 16 * 160];
__device__ uint2 g_w4_3[160 * 16 * 80];
__device__ uint2 g_w4_4[80 * 16 * 40];

// ---------------- f32x2 helpers ----------------
__device__ __forceinline__ void ffma2(ull& d, ull a, ull b) {
    asm("fma.rn.f32x2 %0, %1, %2, %0;" : "+l"(d) : "l"(a), "l"(b));
}
__device__ __forceinline__ ull dup2(float w) {
    ull r;
    asm("mov.b64 %0, {%1, %1};" : "=l"(r) : "f"(w));
    return r;
}
__device__ __forceinline__ float2 u2f2(ull v) {
    float2 f;
    memcpy(&f, &v, 8);
    return f;
}
__device__ __forceinline__ __half2 uh2(unsigned v) {
    __half2 h;
    memcpy(&h, &v, 4);
    return h;
}

// ---------------- prep helpers ----------------
__device__ __forceinline__ void store_w16(uint2* __restrict__ w4, int e, int o, int OUT,
                                          const float* w) {
#pragma unroll
    for (int j = 0; j < 16; j++) {
        int c0 = j - 3;
        float vx = (c0 >= 0 && c0 < 13) ? w[c0] : 0.f;
        float vy = (c0 + 1 >= 0 && c0 + 1 < 13) ? w[c0 + 1] : 0.f;
        float vz = (c0 + 2 >= 0 && c0 + 2 < 13) ? w[c0 + 2] : 0.f;
        float vw = (c0 + 3 >= 0 && c0 + 3 < 13) ? w[c0 + 3] : 0.f;
        __half2 h01 = __floats2half2_rn(vx, vy);
        __half2 h23 = __floats2half2_rn(vz, vw);
        uint2 u;
        u.x = *(unsigned*)&h01;
        u.y = *(unsigned*)&h23;
        w4[(e * 16 + j) * OUT + o] = u;
    }
}

__device__ __forceinline__ void store_wb(float4* __restrict__ wb, int i, int o_slot,
                                         int NU4, float v) {
    int lane = o_slot & 31;
    int t = o_slot >> 5;
    int u = t >> 2;
    int s = t & 3;
    ((float*)wb)[((size_t)(i * NU4 + u) * 32 + lane) * 4 + s] = v;
}

// layer-1 prep: fold duplicated angle features (exact); thread per (e, o_slot<128)
__global__ void prep_l1_kernel(const float* __restrict__ base,
                               const float* __restrict__ spline,
                               const float* __restrict__ scaler,
                               float4* __restrict__ wb,
                               uint2* __restrict__ w4) {
    int tid = blockIdx.x * blockDim.x + threadIdx.x;
    if (tid >= IN1 * 128) return;
    int o_slot = tid & 127;
    int e = tid >> 7;
    if (e >= IN1_EFF || o_slot >= 80) {
        store_wb(wb, e, o_slot, 1, 0.f);
        return;
    }
    int o = o_slot;
    int ch = e / 27, m = e % 27;
    int i = ch * 36 + m;
    float sc = scaler[o * 504 + i];
    const float* sp = spline + (size_t)(o * 504 + i) * 13;
    float w[13];
#pragma unroll
    for (int c = 0; c < 13; c++) w[c] = sp[c] * sc;
    float bsum = base[o * 504 + i];
    if (m >= 9 && m < 18) {
        int i2 = i + 18;
        float sc2 = scaler[o * 504 + i2];
        const float* sp2 = spline + (size_t)(o * 504 + i2) * 13;
#pragma unroll
        for (int c = 0; c < 13; c++) w[c] += sp2[c] * sc2;
        bsum += base[o * 504 + i2];
    }
    store_wb(wb, e, o_slot, 1, bsum);
    store_w16(w4, e, o, 80, w);
}

// layers 2-4 merged prep + twiddle fill; thread per (i, o_slot)
__global__ void prep3_kernel(const float* __restrict__ b2, const float* __restrict__ s2, const float* __restrict__ c2,
                             const float* __restrict__ b3, const float* __restrict__ s3, const float* __restrict__ c3,
                             const float* __restrict__ b4, const float* __restrict__ s4, const float* __restrict__ c4,
                             float4* __restrict__ wb2, uint2* __restrict__ w42,
                             float4* __restrict__ wb3, uint2* __restrict__ w43,
                             float4* __restrict__ wb4, uint2* __restrict__ w44,
                             float* __restrict__ tw) {
    int tid = blockIdx.x * blockDim.x + threadIdx.x;
    const int N2 = 80 * 256, N3 = 160 * 128, N4 = 80 * 128;
    const int NTOT = N2 + N3 + N4;
    if (tid >= NTOT) {
        int t2 = tid - NTOT;
        if (t2 < 288) {
            int k = t2 >> 5, n = t2 & 31;
            float s, c;
            sincospif((float)(k * n) * (1.0f / 16.0f), &s, &c);
            tw[t2] = c;
            tw[t2 + 288] = s;
        }
        return;
    }
    const float *base, *spline, *scaler;
    float4* wb;
    uint2* w4;
    int IN, OUT, NU4, local;
    if (tid < N2) {
        base = b2; spline = s2; scaler = c2; wb = wb2; w4 = w42; IN = 80; OUT = 160; NU4 = 2; local = tid;
    } else if (tid < N2 + N3) {
        base = b3; spline = s3; scaler = c3; wb = wb3; w4 = w43; IN = 160; OUT = 80; NU4 = 1; local = tid - N2;
    } else {
        base = b4; spline = s4; scaler = c4; wb = wb4; w4 = w44; IN = 80; OUT = 40; NU4 = 1; local = tid - N2 - N3;
    }
    int SLOTS = NU4 * 128;
    int o_slot = local % SLOTS;
    int i = local / SLOTS;
    if (o_slot >= OUT) {
        store_wb(wb, i, o_slot, NU4, 0.f);
        return;
    }
    int o = o_slot;
    store_wb(wb, i, o_slot, NU4, base[o * IN + i]);
    float sc = scaler[o * IN + i];
    const float* sp = spline + (size_t)(o * IN + i) * 13;
    float w[13];
#pragma unroll
    for (int c = 0; c < 13; c++) w[c] = sp[c] * sc;
    store_w16(w4, i, o, OUT, w);
}

// ---------------- FFT feature kernel: transposed smem, conflict-free inner loop ----------------
__global__ void fft_kernel(const float* __restrict__ x, const float* __restrict__ tw,
                           float* __restrict__ h0) {
    __shared__ float sx[64][17];    // [n][c]: lanes differ in c -> distinct banks
    __shared__ float sco[32][12];   // [n][k]: lanes differ in k -> distinct banks
    __shared__ float ssi[32][12];
    int b = blockIdx.x;
    int t = threadIdx.x;
    const float* xb = x + (size_t)b * 896;
    for (int i = t; i < 896; i += 128) {
        int c = i / 64, n = i % 64;
        sx[n][c] = xb[i];
    }
    for (int i = t; i < 384; i += 128) {
        int n = i / 12, k = i % 12;
        float cv = 0.f, sv = 0.f;
        if (k < 9) {
            cv = __ldg(&tw[k * 32 + n]);
            sv = __ldg(&tw[288 + k * 32 + n]);
        }
        sco[n][k] = cv;
        ssi[n][k] = sv;
    }
    __syncthreads();
    if (t < 6) h0[(size_t)b * IN1 + IN1_EFF + t] = -1e9f;
    if (t < 126) {
        int c = t / 9, k = t % 9;
        float pr = 0.f, pi = 0.f, cr = 0.f, ci = 0.f;
#pragma unroll
        for (int n = 0; n < 32; n++) {
            float co = sco[n][k], si = ssi[n][k];
            float a = sx[n][c], d = sx[n + 32][c];
            pr += a * co; pi -= a * si;
            cr += d * co; ci -= d * si;
        }
        float abs_p = sqrtf(pr * pr + pi * pi);
        float abs_c = sqrtf(cr * cr + ci * ci);
        float ang_c = atan2f(ci, cr);
        float* o = h0 + (size_t)b * IN1 + c * 27;
        o[k] = abs_p;
        o[9 + k] = ang_c;
        o[18 + k] = abs_c;
    }
}

// ---------------- base path v6: 4-way split-K, 8 rows/warp, f32x2 packed FMA ----------------
// ADD=true: accumulate into existing out (used when spline ran first)
template <int IN, int OUT, int NO, int NU4, bool ADD>
__global__ void __launch_bounds__(256) base_gemm6(const float* __restrict__ xin,
                                                  const float4* __restrict__ wbp,
                                                  float* __restrict__ out) {
    __shared__ __align__(16) float ss[IN][20];   // [i][row 0..15], pad 4
    __shared__ float2 pacc[3][8][NO * 32];       // partials from splits 1..3, per row-pair
    int b0 = blockIdx.x * 16;
    int tid = threadIdx.x;
    constexpr int NF4 = IN / 4;
    {
        int r = tid & 15;
        const float4* xp = (const float4*)(xin + (size_t)(b0 + r) * IN);
        for (int i4 = tid >> 4; i4 < NF4; i4 += 16) {
            float4 v = xp[i4];
            v.x = v.x / (1.f + __expf(-v.x));
            v.y = v.y / (1.f + __expf(-v.y));
            v.z = v.z / (1.f + __expf(-v.z));
            v.w = v.w / (1.f + __expf(-v.w));
            ss[i4 * 4 + 0][r] = v.x;
            ss[i4 * 4 + 1][r] = v.y;
            ss[i4 * 4 + 2][r] = v.z;
            ss[i4 * 4 + 3][r] = v.w;
        }
    }
    __syncthreads();

    int w = tid >> 5, lane = tid & 31;
    int rg = w & 1;
    int sp = w >> 1;
    int r0 = rg * 8;
    constexpr int KH = IN / 4;
    int istart = sp * KH;

    ull acc[4][NO];   // [row-pair][slot], packed (even,odd) rows
#pragma unroll
    for (int pp = 0; pp < 4; pp++)
#pragma unroll
        for (int q = 0; q < NO; q++) acc[pp][q] = 0ull;

#pragma unroll 4
    for (int ii = 0; ii < KH; ii++) {
        int i = istart + ii;
        longlong2 sa = *(const longlong2*)&ss[i][r0];       // (s0,s1),(s2,s3)
        longlong2 sb = *(const longlong2*)&ss[i][r0 + 4];   // (s4,s5),(s6,s7)
#pragma unroll
        for (int u = 0; u < NU4; u++) {
            float4 wv = __ldg(&wbp[(size_t)(i * NU4 + u) * 32 + lane]);
#pragma unroll
            for (int c = 0; c < 4; c++) {
                int q = u * 4 + c;
                if (q < NO) {
                    float wf = (c == 0) ? wv.x : (c == 1) ? wv.y : (c == 2) ? wv.z : wv.w;
                    ull wd = dup2(wf);
                    ffma2(acc[0][q], (ull)sa.x, wd);
                    ffma2(acc[1][q], (ull)sa.y, wd);
                    ffma2(acc[2][q], (ull)sb.x, wd);
                    ffma2(acc[3][q], (ull)sb.y, wd);
                }
            }
        }
    }

    if (sp > 0) {
#pragma unroll
        for (int pp = 0; pp < 4; pp++)
#pragma unroll
            for (int q = 0; q < NO; q++)
                pacc[sp - 1][rg * 4 + pp][lane + q * 32] = u2f2(acc[pp][q]);
    }
    __syncthreads();
    if (sp == 0) {
#pragma unroll
        for (int pp = 0; pp < 4; pp++) {
#pragma unroll
            for (int q = 0; q < NO; q++) {
                int o = lane + q * 32;
                if (o < OUT) {
                    int idx = lane + q * 32;
                    int rp = rg * 4 + pp;
                    float2 t = u2f2(acc[pp][q]);
                    float2 p0 = pacc[0][rp][idx];
                    float2 p1 = pacc[1][rp][idx];
                    float2 p2 = pacc[2][rp][idx];
                    size_t o0 = (size_t)(b0 + r0 + pp * 2 + 0) * OUT + o;
                    size_t o1 = (size_t)(b0 + r0 + pp * 2 + 1) * OUT + o;
                    float v0 = t.x + p0.x + p1.x + p2.x;
                    float v1 = t.y + p0.y + p1.y + p2.y;
                    if (ADD) {
                        out[o0] = v0 + out[o0];
                        out[o1] = v1 + out[o1];
                    } else {
                        out[o0] = v0;
                        out[o1] = v1;
                    }
                }
            }
        }
    }
}

// ---------------- spline path v2.3: fp16 bases in smem, HFMA2 inner, oct-unrolled gather ----------------
// INIT=true: start acc from 0 (runs before base, which then adds)
template <int IN, int IEFF, int OUT, int NO, bool INIT>
__global__ void __launch_bounds__(128, 8) spline_kernel(const float* __restrict__ xin,
                                                        const uint2* __restrict__ w4,
                                                        float* __restrict__ out) {
    constexpr int R = 4;
    __shared__ uint2 sbs[R][IEFF];      // bases as 2x half2
    __shared__ int scode[R][IEFF];
    int r = threadIdx.x >> 5;
    int lane = threadIdx.x & 31;
    int b = blockIdx.x * R + r;
    const float* xr = xin + (size_t)b * IN;

    int cnt = 0;
    for (int i0 = 0; i0 < IEFF; i0 += 32) {
        int i = i0 + lane;
        bool valid = false;
        int j = 0;
        float4 bs = make_float4(0.f, 0.f, 0.f, 0.f);
        if (i < IEFF) {
            float xv = xr[i];
            float u = (xv + 0.3f) * 10.0f;
            j = (int)floorf(u);
            if (j >= 0 && j <= 15) {
                float gj = (float)(j - 3) * 0.1f;
                float t = (xv - gj) * 10.0f;
                float t2 = t * t, t3 = t2 * t;
                float omt = 1.f - t;
                bs.x = omt * omt * omt * (1.f / 6.f);
                bs.y = (3.f * t3 - 6.f * t2 + 4.f) * (1.f / 6.f);
                bs.z = (-3.f * t3 + 3.f * t2 + 3.f * t + 1.f) * (1.f / 6.f);
                bs.w = t3 * (1.f / 6.f);
                valid = true;
            }
        }
        unsigned m = __ballot_sync(0xffffffffu, valid);
        int pos = cnt + __popc(m & ((1u << lane) - 1u));
        if (valid) {
            scode[r][pos] = i * 16 + j;
            __half2 h01 = __floats2half2_rn(bs.x, bs.y);
            __half2 h23 = __floats2half2_rn(bs.z, bs.w);
            uint2 u;
            u.x = *(unsigned*)&h01;
            u.y = *(unsigned*)&h23;
            sbs[r][pos] = u;
        }
        cnt += __popc(m);
    }
    __syncwarp();

    float acc[NO];
#pragma unroll
    for (int q = 0; q < NO; q++) {
        int o = lane + q * 32;
        acc[q] = (!INIT && o < OUT) ? out[(size_t)b * OUT + o] : 0.f;
    }

    int e = 0;
    // oct-unrolled: 8 entries -> up to 8*NO independent LDG.64 in flight
    for (; e + 8 <= cnt; e += 8) {
        __half2 b01[8], b23[8];
        const uint2* wp[8];
#pragma unroll
        for (int k = 0; k < 8; k++) {
            int c = scode[r][e + k];
            uint2 ub = sbs[r][e + k];
            b01[k] = uh2(ub.x);
            b23[k] = uh2(ub.y);
            wp[k] = w4 + (size_t)c * OUT;
        }
#pragma unroll
        for (int q = 0; q < NO; q++) {
            int o = lane + q * 32;
            int oc = (o < OUT) ? o : (OUT - 1);
            uint2 uu[8];
#pragma unroll
            for (int k = 0; k < 8; k++) uu[k] = __ldg(&wp[k][oc]);
            __half2 hacc = __floats2half2_rn(0.f, 0.f);
#pragma unroll
            for (int k = 0; k < 8; k++) {
                hacc = __hfma2(uh2(uu[k].x), b01[k], hacc);
                hacc = __hfma2(uh2(uu[k].y), b23[k], hacc);
            }
            float2 f = __half22float2(hacc);
            if (o < OUT) acc[q] += f.x + f.y;
        }
    }
    for (; e + 4 <= cnt; e += 4) {
        __half2 b01[4], b23[4];
        const uint2* wp[4];
#pragma unroll
        for (int k = 0; k < 4; k++) {
            int c = scode[r][e + k];
            uint2 ub = sbs[r][e + k];
            b01[k] = uh2(ub.x);
            b23[k] = uh2(ub.y);
            wp[k] = w4 + (size_t)c * OUT;
        }
#pragma unroll
        for (int q = 0; q < NO; q++) {
            int o = lane + q * 32;
            int oc = (o < OUT) ? o : (OUT - 1);
            uint2 u0 = __ldg(&wp[0][oc]);
            uint2 u1 = __ldg(&wp[1][oc]);
            uint2 u2 = __ldg(&wp[2][oc]);
            uint2 u3 = __ldg(&wp[3][oc]);
            __half2 hacc = __floats2half2_rn(0.f, 0.f);
            hacc = __hfma2(uh2(u0.x), b01[0], hacc);
            hacc = __hfma2(uh2(u0.y), b23[0], hacc);
            hacc = __hfma2(uh2(u1.x), b01[1], hacc);
            hacc = __hfma2(uh2(u1.y), b23[1], hacc);
            hacc = __hfma2(uh2(u2.x), b01[2], hacc);
            hacc = __hfma2(uh2(u2.y), b23[2], hacc);
            hacc = __hfma2(uh2(u3.x), b01[3], hacc);
            hacc = __hfma2(uh2(u3.y), b23[3], hacc);
            float2 f = __half22float2(hacc);
            if (o < OUT) acc[q] += f.x + f.y;
        }
    }
    for (; e < cnt; e++) {
        int c0 = scode[r][e];
        uint2 ub = sbs[r][e];
        __half2 b01 = uh2(ub.x);
        __half2 b23 = uh2(ub.y);
        const uint2* w0 = w4 + (size_t)c0 * OUT;
#pragma unroll
        for (int q = 0; q < NO; q++) {
            int o = lane + q * 32;
            int oc = (o < OUT) ? o : (OUT - 1);
            uint2 ua = __ldg(&w0[oc]);
            __half2 hacc = __floats2half2_rn(0.f, 0.f);
            hacc = __hfma2(uh2(ua.x), b01, hacc);
            hacc = __hfma2(uh2(ua.y), b23, hacc);
            float2 f = __half22float2(hacc);
            if (o < OUT) acc[q] += f.x + f.y;
        }
    }
#pragma unroll
    for (int q = 0; q < NO; q++) {
        int o = lane + q * 32;
        if (o < OUT) out[(size_t)b * OUT + o] = acc[q];
    }
}

// ---------------- heads: 3 small MLPs, weights staged in shared ----------------
__global__ void heads_kernel(const float* __restrict__ h4,
                             const float* __restrict__ W1, const float* __restrict__ b1,
                             const float* __restrict__ W2, const float* __restrict__ b2,
                             const float* __restrict__ W3, const float* __restrict__ b3,
                             float* __restrict__ out) {
    int head = blockIdx.y;
    __shared__ float sW1[1600], sb1v[40], sW2[800], sb2v[20], sW3[20];
    int t = threadIdx.x;
    for (int i = t; i < 1600; i += 128) sW1[i] = W1[head * 1600 + i];
    for (int i = t; i < 800; i += 128) sW2[i] = W2[head * 800 + i];
    if (t < 40) sb1v[t] = b1[head * 40 + t];
    if (t < 20) {
        sb2v[t] = b2[head * 20 + t];
        sW3[t] = W3[head * 20 + t];
    }
    __syncthreads();
    int b = blockIdx.x * 128 + t;
    float hv[40];
    const float4* hp = (const float4*)(h4 + (size_t)b * 40);
#pragma unroll
    for (int i = 0; i < 10; i++) {
        float4 v = hp[i];
        hv[i * 4 + 0] = v.x; hv[i * 4 + 1] = v.y; hv[i * 4 + 2] = v.z; hv[i * 4 + 3] = v.w;
    }
    float y1[40];
#pragma unroll
    for (int j = 0; j < 40; j++) {
        float s = sb1v[j];
#pragma unroll
        for (int k = 0; k < 40; k++) s += sW1[j * 40 + k] * hv[k];
        y1[j] = s;  // LeakyReLU(True) -> slope 1 -> identity
    }
    float y3 = b3[head];
#pragma unroll
    for (int j = 0; j < 20; j++) {
        float s = sb2v[j];
#pragma unroll
        for (int k = 0; k < 40; k++) s += sW2[j * 40 + k] * y1[k];
        s = (s >= 0.f) ? s : 0.05f * s;
        y3 += sW3[j] * s;
    }
    out[(size_t)b * 3 + head] = 1.f / (1.f + __expf(-y3));
}

// ---------------- launch ----------------
extern "C" void kernel_launch(void* const* d_in, const int* in_sizes, int n_in,
                              void* d_out, int out_size) {
    const float* x   = (const float*)d_in[0];
    const float* k1b = (const float*)d_in[1];
    const float* k1s = (const float*)d_in[2];
    const float* k1c = (const float*)d_in[3];
    const float* k2b = (const float*)d_in[4];
    const float* k2s = (const float*)d_in[5];
    const float* k2c = (const float*)d_in[6];
    const float* k3b = (const float*)d_in[7];
    const float* k3s = (const float*)d_in[8];
    const float* k3c = (const float*)d_in[9];
    const float* k4b = (const float*)d_in[10];
    const float* k4s = (const float*)d_in[11];
    const float* k4c = (const float*)d_in[12];
    const float* hW1 = (const float*)d_in[13];
    const float* hb1 = (const float*)d_in[14];
    const float* hW2 = (const float*)d_in[15];
    const float* hb2 = (const float*)d_in[16];
    const float* hW3 = (const float*)d_in[17];
    const float* hb3 = (const float*)d_in[18];
    float* out = (float*)d_out;

    float *h0, *h1, *h2, *h3, *h4, *tw;
    float4 *wb1, *wb2, *wb3, *wb4;
    uint2 *w41, *w42, *w43, *w44;
    cudaGetSymbolAddress((void**)&h0, g_h0);
    cudaGetSymbolAddress((void**)&h1, g_h1);
    cudaGetSymbolAddress((void**)&h2, g_h2);
    cudaGetSymbolAddress((void**)&h3, g_h3);
    cudaGetSymbolAddress((void**)&h4, g_h4);
    cudaGetSymbolAddress((void**)&tw, g_tw);
    cudaGetSymbolAddress((void**)&wb1, g_wb1);
    cudaGetSymbolAddress((void**)&wb2, g_wb2);
    cudaGetSymbolAddress((void**)&wb3, g_wb3);
    cudaGetSymbolAddress((void**)&wb4, g_wb4);
    cudaGetSymbolAddress((void**)&w41, g_w4_1);
    cudaGetSymbolAddress((void**)&w42, g_w4_2);
    cudaGetSymbolAddress((void**)&w43, g_w4_3);
    cudaGetSymbolAddress((void**)&w44, g_w4_4);

    prep_l1_kernel<<<(IN1 * 128 + 255) / 256, 256>>>(k1b, k1s, k1c, wb1, w41);
    prep3_kernel<<<(80 * 256 + 160 * 128 + 80 * 128 + 288 + 255) / 256, 256>>>(
        k2b, k2s, k2c, k3b, k3s, k3c, k4b, k4s, k4c,
        wb2, w42, wb3, w43, wb4, w44, tw);

    fft_kernel<<<NB, 128>>>(x, tw, h0);

    // layer 1: spline first (launch #4 -> ncu capture), base adds
    spline_kernel<IN1, IN1_EFF, 80, 3, true><<<NB / 4, 128>>>(h0, w41, h1);
    base_gemm6<IN1, 80, 3, 1, true><<<NB / 16, 256>>>(h0, wb1, h1);

    base_gemm6<80, 160, 5, 2, false><<<NB / 16, 256>>>(h1, wb2, h2);
    spline_kernel<80, 80, 160, 5, false><<<NB / 4, 128>>>(h1, w42, h2);

    base_gemm6<160, 80, 3, 1, false><<<NB / 16, 256>>>(h2, wb3, h3);
    spline_kernel<160, 160, 80, 3, false><<<NB / 4, 128>>>(h2, w43, h3);

    base_gemm6<80, 40, 2, 1, false><<<NB / 16, 256>>>(h3, wb4, h4);
    spline_kernel<80, 80, 40, 2, false><<<NB / 4, 128>>>(h3, w44, h4);

    heads_kernel<<<dim3(NB / 128, 3), 128>>>(h4, hW1, hb1, hW2, hb2, hW3, hb3, out);
}